// round 4
// baseline (speedup 1.0000x reference)
#include <cuda_runtime.h>
#include <cuda_bf16.h>
#include <cstdint>

#define TOKENS 16384
#define DMODEL 768
#define DFFN   3072
#define NHEAD  8
#define HDIM   96
#define NBLK   64
#define BLKS   64
#define NKBS   5
#define SEQ    4096
#define BATCH  4

// ---------------- scratch (static device globals; no allocation) ----------------
// plane layout: X[row][plane][k], plane 0 = bf16 hi, plane 1 = bf16 lo. row stride 2*K.
__device__ __nv_bfloat16 g_hP  [TOKENS * 2 * DMODEL];
__device__ __nv_bfloat16 g_ctxP[TOKENS * 2 * DMODEL];
__device__ __nv_bfloat16 g_ffnP[TOKENS * 2 * DFFN];
__device__ float         g_q   [TOKENS * DMODEL];
__device__ float         g_k   [TOKENS * DMODEL];
__device__ float         g_v   [TOKENS * DMODEL];
__device__ float         g_x   [TOKENS * DMODEL];
__device__ __nv_bfloat16 g_wqT [DMODEL * 2 * DMODEL];   // [n][plane][k]
__device__ __nv_bfloat16 g_wkT [DMODEL * 2 * DMODEL];
__device__ __nv_bfloat16 g_wvT [DMODEL * 2 * DMODEL];
__device__ __nv_bfloat16 g_woT [DMODEL * 2 * DMODEL];
__device__ __nv_bfloat16 g_w1T [DFFN * 2 * DMODEL];
__device__ __nv_bfloat16 g_w2T [DMODEL * 2 * DFFN];

// ---------------- helpers ----------------
__device__ __forceinline__ uint32_t smem_u32(const void* p) {
    uint32_t a;
    asm("{ .reg .u64 t; cvta.to.shared.u64 t, %1; cvt.u32.u64 %0, t; }" : "=r"(a) : "l"(p));
    return a;
}
__device__ __forceinline__ void split_bf(float v, __nv_bfloat16& h, __nv_bfloat16& l) {
    h = __float2bfloat16(v);
    l = __float2bfloat16(v - __bfloat162float(h));
}
__device__ __forceinline__ void mma16816(float* c, uint32_t a0, uint32_t a1, uint32_t a2,
                                         uint32_t a3, uint32_t b0, uint32_t b1) {
    asm volatile(
        "mma.sync.aligned.m16n8k16.row.col.f32.bf16.bf16.f32 "
        "{%0,%1,%2,%3}, {%4,%5,%6,%7}, {%8,%9}, {%0,%1,%2,%3};"
        : "+f"(c[0]), "+f"(c[1]), "+f"(c[2]), "+f"(c[3])
        : "r"(a0), "r"(a1), "r"(a2), "r"(a3), "r"(b0), "r"(b1));
}
#define LDM4(r, addr)                                                      \
    asm volatile("ldmatrix.sync.aligned.m8n8.x4.shared.b16 {%0,%1,%2,%3}, [%4];" \
                 : "=r"((r)[0]), "=r"((r)[1]), "=r"((r)[2]), "=r"((r)[3]) : "r"(addr))
#define CP16(dst, src) \
    asm volatile("cp.async.cg.shared.global [%0], [%1], 16;" :: "r"(dst), "l"(src))
#define CP_COMMIT() asm volatile("cp.async.commit_group;" ::: "memory")
#define CP_WAIT2()  asm volatile("cp.async.wait_group 2;" ::: "memory")

// ---------------- bf16x3 tensor-core GEMM (plane layout + ldmatrix) ----------------
// C[M,N] = A[M,K] @ W[K,N] via BT[N][plane][K]. BM=BN=128, BK=32, 8 warps (64x32 each),
// 3-stage cp.async. smem tile: per stage {Ahi, Alo, Bhi, Blo}, each 128 rows x 64B,
// chunk swizzle c' = c ^ ((r>>1)&3)  (conflict-free ldmatrix phases).
#define PLN   8192                   // bytes per plane tile
#define OPB   16384                  // bytes per operand (2 planes)
#define STG   32768                  // bytes per stage
#define GSMEM (3 * STG)              // 98304

__global__ void __launch_bounds__(256) gemm_bf3_kernel(const __nv_bfloat16* __restrict__ A,
                                                       const __nv_bfloat16* __restrict__ BT,
                                                       const float* __restrict__ bias,
                                                       const float* __restrict__ resid,
                                                       float* __restrict__ C,
                                                       __nv_bfloat16* __restrict__ Cp,
                                                       int K, int N, int relu) {
    extern __shared__ char smem[];
    uint32_t sbase = smem_u32(smem);
    int tid  = threadIdx.x;
    int brow = blockIdx.y * 128;
    int bcol = blockIdx.x * 128;

    int w = tid >> 5, lane = tid & 31;
    int g = lane >> 2, tg = lane & 3;
    int wm = (w >> 2) * 64;          // 0 or 64
    int wn = (w & 3) * 32;           // 0,32,64,96

    // ldmatrix lane geometry
    int rlA  = ((lane >> 3) & 1) * 8 + (lane & 7);
    int kbA  = (lane >> 4) & 1;
    int selA = (rlA >> 1) & 3;
    int rlB  = ((lane >> 4) & 1) * 8 + (lane & 7);
    int kbB  = (lane >> 3) & 1;
    int selB = (rlB >> 1) & 3;

    // fetch assignment: thread -> operand o (A/B), row r; copies 2 planes x 4 chunks
    int fo = tid >> 7;               // 0 = A, 1 = B
    int fr = tid & 127;
    const __nv_bfloat16* gsrc =
        fo ? (BT + ((size_t)(bcol + fr) * 2) * K) : (A + ((size_t)(brow + fr) * 2) * K);
    uint32_t fdst_base = (uint32_t)fo * OPB + (uint32_t)fr * 64;
    uint32_t fswz = (uint32_t)((fr >> 1) & 3);
    int nch = K >> 5;

#define FETCH(stage, kc) do {                                                       \
    uint32_t d_ = sbase + (stage) * STG + fdst_base;                                \
    const __nv_bfloat16* s_ = gsrc + (kc) * 32;                                     \
    CP16(d_ + ((0u ^ fswz) << 4),       s_ + 0);                                    \
    CP16(d_ + ((1u ^ fswz) << 4),       s_ + 8);                                    \
    CP16(d_ + ((2u ^ fswz) << 4),       s_ + 16);                                   \
    CP16(d_ + ((3u ^ fswz) << 4),       s_ + 24);                                   \
    CP16(d_ + PLN + ((0u ^ fswz) << 4), s_ + K + 0);                                \
    CP16(d_ + PLN + ((1u ^ fswz) << 4), s_ + K + 8);                                \
    CP16(d_ + PLN + ((2u ^ fswz) << 4), s_ + K + 16);                               \
    CP16(d_ + PLN + ((3u ^ fswz) << 4), s_ + K + 24);                               \
} while (0)

    float acc[4][4][4];
#pragma unroll
    for (int mt = 0; mt < 4; mt++)
#pragma unroll
        for (int nt = 0; nt < 4; nt++)
#pragma unroll
            for (int j = 0; j < 4; j++) acc[mt][nt][j] = 0.f;

    FETCH(0, 0); CP_COMMIT();
    FETCH(1, 1); CP_COMMIT();

    int stage = 0;
    for (int c = 0; c < nch; c++) {
        int fs = c + 2;
        if (fs < nch) { int st = fs - (fs / 3) * 3; FETCH(st, fs); }
        CP_COMMIT();
        CP_WAIT2();
        __syncthreads();

        uint32_t sa = sbase + stage * STG;
#pragma unroll
        for (int h = 0; h < 2; h++) {
            uint32_t ah[4][4], al[4][4];
            uint32_t cA = (uint32_t)(((h * 2 + kbA) ^ selA) << 4);
#pragma unroll
            for (int mt = 0; mt < 4; mt++) {
                uint32_t base = sa + (uint32_t)((wm + mt * 16 + rlA) * 64) + cA;
                LDM4(ah[mt], base);
                LDM4(al[mt], base + PLN);
            }
            uint32_t cB = (uint32_t)(((h * 2 + kbB) ^ selB) << 4);
#pragma unroll
            for (int np = 0; np < 2; np++) {
                uint32_t bb = sa + OPB + (uint32_t)((wn + np * 16 + rlB) * 64) + cB;
                uint32_t bh[4], bl[4];
                LDM4(bh, bb);
                LDM4(bl, bb + PLN);
#pragma unroll
                for (int q = 0; q < 2; q++) {
                    int nt = np * 2 + q;
#pragma unroll
                    for (int mt = 0; mt < 4; mt++) {
                        mma16816(acc[mt][nt], ah[mt][0], ah[mt][1], ah[mt][2], ah[mt][3],
                                 bh[q * 2], bh[q * 2 + 1]);
                        mma16816(acc[mt][nt], ah[mt][0], ah[mt][1], ah[mt][2], ah[mt][3],
                                 bl[q * 2], bl[q * 2 + 1]);
                        mma16816(acc[mt][nt], al[mt][0], al[mt][1], al[mt][2], al[mt][3],
                                 bh[q * 2], bh[q * 2 + 1]);
                    }
                }
            }
        }
        __syncthreads();
        stage++; if (stage == 3) stage = 0;
    }

    // epilogue
#pragma unroll
    for (int mt = 0; mt < 4; mt++) {
#pragma unroll
        for (int half = 0; half < 2; half++) {
            int r = brow + wm + mt * 16 + g + half * 8;
#pragma unroll
            for (int nt = 0; nt < 4; nt++) {
                int col = bcol + wn + nt * 8 + tg * 2;
                float v0 = acc[mt][nt][half * 2 + 0] + __ldg(&bias[col + 0]);
                float v1 = acc[mt][nt][half * 2 + 1] + __ldg(&bias[col + 1]);
                if (relu) { v0 = fmaxf(v0, 0.f); v1 = fmaxf(v1, 0.f); }
                size_t off = (size_t)r * N + col;
                if (resid) {
                    float2 rv = *(const float2*)(resid + off);
                    v0 += rv.x; v1 += rv.y;
                }
                if (Cp) {
                    __nv_bfloat16 h0, l0, h1, l1;
                    split_bf(v0, h0, l0);
                    split_bf(v1, h1, l1);
                    __nv_bfloat162 hv; hv.x = h0; hv.y = h1;
                    __nv_bfloat162 lv; lv.x = l0; lv.y = l1;
                    *(__nv_bfloat162*)(Cp + ((size_t)r * 2) * N + col)     = hv;
                    *(__nv_bfloat162*)(Cp + ((size_t)r * 2 + 1) * N + col) = lv;
                } else {
                    float2 fv; fv.x = v0; fv.y = v1;
                    *(float2*)(C + off) = fv;
                }
            }
        }
    }
}

// ---------------- weight transpose + split: out[n][plane][k] from in[k][n] ----------------
__global__ void __launch_bounds__(256) transpose_pack_kernel(const float* __restrict__ in,
                                                             __nv_bfloat16* __restrict__ out,
                                                             int R, int Ccols) {
    __shared__ float t[32][33];
    int bx = blockIdx.x * 32, by = blockIdx.y * 32;
    int x = threadIdx.x & 31, y = threadIdx.x >> 5;
#pragma unroll
    for (int j = 0; j < 32; j += 8)
        t[y + j][x] = in[(size_t)(by + y + j) * Ccols + bx + x];
    __syncthreads();
#pragma unroll
    for (int j = 0; j < 32; j += 8) {
        __nv_bfloat16 h, l;
        split_bf(t[x][y + j], h, l);
        size_t nrow = (size_t)(bx + y + j) * 2;
        out[nrow * R + by + x]       = h;
        out[(nrow + 1) * R + by + x] = l;
    }
}

// ---------------- LayerNorm -> bf16 planes ----------------
__global__ void __launch_bounds__(256) ln_pack_kernel(const float* __restrict__ x,
                                                      const float* __restrict__ gam,
                                                      const float* __restrict__ bet,
                                                      __nv_bfloat16* __restrict__ out) {
    int row = blockIdx.x;
    const float* xr = x + (size_t)row * DMODEL;
    int t = threadIdx.x;
    float v0 = xr[t], v1 = xr[t + 256], v2 = xr[t + 512];
    float s  = v0 + v1 + v2;
    float sq = v0 * v0 + v1 * v1 + v2 * v2;
#pragma unroll
    for (int o = 16; o; o >>= 1) {
        s  += __shfl_xor_sync(0xffffffffu, s, o);
        sq += __shfl_xor_sync(0xffffffffu, sq, o);
    }
    __shared__ float rs_[8], rq_[8];
    if ((t & 31) == 0) { rs_[t >> 5] = s; rq_[t >> 5] = sq; }
    __syncthreads();
    s = 0.f; sq = 0.f;
#pragma unroll
    for (int ww = 0; ww < 8; ww++) { s += rs_[ww]; sq += rq_[ww]; }
    float m   = s * (1.f / DMODEL);
    float var = sq * (1.f / DMODEL) - m * m;
    float inv = rsqrtf(var + 1e-5f);
    __nv_bfloat16* hiR = out + (size_t)row * 2 * DMODEL;
    __nv_bfloat16* loR = hiR + DMODEL;
    __nv_bfloat16 h, l;
    split_bf((v0 - m) * inv * gam[t] + bet[t], h, l);
    hiR[t] = h; loR[t] = l;
    split_bf((v1 - m) * inv * gam[t + 256] + bet[t + 256], h, l);
    hiR[t + 256] = h; loR[t + 256] = l;
    split_bf((v2 - m) * inv * gam[t + 512] + bet[t + 512], h, l);
    hiR[t + 512] = h; loR[t + 512] = l;
}

// ---------------- BigBird block attention (fp32 in, bf16 planes out) ----------------
#define QS  97
#define KTS 68
#define VS  97
#define SCS 324
#define OFF_Q   0
#define OFF_KV  (64 * QS)
#define OFF_SC  (OFF_KV + 96 * KTS)
#define OFF_INV (OFF_SC + 64 * SCS)
#define ATTN_SMEM_BYTES ((OFF_INV + 64) * 4)

__global__ void __launch_bounds__(256) attn_kernel(const float* __restrict__ Q,
                                                   const float* __restrict__ K,
                                                   const float* __restrict__ V,
                                                   const int* __restrict__ kb_idx,
                                                   __nv_bfloat16* __restrict__ ctxP) {
    extern __shared__ float sm[];
    float* q_s  = sm + OFF_Q;
    float* kv   = sm + OFF_KV;
    float* sc   = sm + OFF_SC;
    float* rinv = sm + OFF_INV;

    int i  = blockIdx.x;
    int hh = blockIdx.y;
    int b  = blockIdx.z;
    int tid = threadIdx.x;
    int base = b * SEQ + i * BLKS;
    const float scale = rsqrtf((float)HDIM);

    for (int idx = tid; idx < BLKS * HDIM; idx += 256) {
        int qq = idx / HDIM, d = idx % HDIM;
        q_s[qq * QS + d] = Q[(size_t)(base + qq) * DMODEL + hh * HDIM + d] * scale;
    }

    int  kbv[NKBS];
    bool val[NKBS], dia[NKBS];
#pragma unroll
    for (int s = 0; s < NKBS; s++) {
        kbv[s] = kb_idx[i * NKBS + s];
        val[s] = (s == 0) || (kbv[s] != 0);
        dia[s] = (kbv[s] == i);
    }

    int sq0 = (tid >> 4) * 4;
    int sp0 = (tid & 15) * 4;
    __syncthreads();

    for (int s = 0; s < NKBS; s++) {
        if (val[s]) {
            __syncthreads();
            int kbase = b * SEQ + kbv[s] * BLKS;
            for (int idx = tid; idx < BLKS * HDIM; idx += 256) {
                int p = idx / HDIM, d = idx % HDIM;
                kv[d * KTS + p] = K[(size_t)(kbase + p) * DMODEL + hh * HDIM + d];
            }
            __syncthreads();
            float acc00=0,acc01=0,acc02=0,acc03=0;
            float acc10=0,acc11=0,acc12=0,acc13=0;
            float acc20=0,acc21=0,acc22=0,acc23=0;
            float acc30=0,acc31=0,acc32=0,acc33=0;
#pragma unroll 4
            for (int d = 0; d < HDIM; d++) {
                float4 bv = *(const float4*)&kv[d * KTS + sp0];
                float a0 = q_s[(sq0 + 0) * QS + d];
                float a1 = q_s[(sq0 + 1) * QS + d];
                float a2 = q_s[(sq0 + 2) * QS + d];
                float a3 = q_s[(sq0 + 3) * QS + d];
                acc00 += a0*bv.x; acc01 += a0*bv.y; acc02 += a0*bv.z; acc03 += a0*bv.w;
                acc10 += a1*bv.x; acc11 += a1*bv.y; acc12 += a1*bv.z; acc13 += a1*bv.w;
                acc20 += a2*bv.x; acc21 += a2*bv.y; acc22 += a2*bv.z; acc23 += a2*bv.w;
                acc30 += a3*bv.x; acc31 += a3*bv.y; acc32 += a3*bv.z; acc33 += a3*bv.w;
            }
            bool dg = dia[s];
            float r[4][4] = {{acc00,acc01,acc02,acc03},{acc10,acc11,acc12,acc13},
                             {acc20,acc21,acc22,acc23},{acc30,acc31,acc32,acc33}};
#pragma unroll
            for (int a = 0; a < 4; a++)
#pragma unroll
                for (int c = 0; c < 4; c++) {
                    int qq = sq0 + a, p = sp0 + c;
                    float v = r[a][c];
                    if (dg && p > qq) v = -1e9f;
                    sc[qq * SCS + s * BLKS + p] = v;
                }
        } else {
            for (int idx = tid; idx < BLKS * BLKS; idx += 256) {
                int qq = idx >> 6, p = idx & 63;
                sc[qq * SCS + s * BLKS + p] = -1e9f;
            }
        }
    }
    __syncthreads();

    {
        int qq = tid >> 2, l4 = tid & 3;
        float* row = sc + qq * SCS;
        float m = -1e30f;
        for (int idx = l4; idx < NKBS * BLKS; idx += 4) m = fmaxf(m, row[idx]);
        m = fmaxf(m, __shfl_xor_sync(0xffffffffu, m, 1));
        m = fmaxf(m, __shfl_xor_sync(0xffffffffu, m, 2));
        float ss = 0.f;
        for (int idx = l4; idx < NKBS * BLKS; idx += 4) {
            float e = __expf(row[idx] - m);
            row[idx] = e;
            ss += e;
        }
        ss += __shfl_xor_sync(0xffffffffu, ss, 1);
        ss += __shfl_xor_sync(0xffffffffu, ss, 2);
        if (l4 == 0) rinv[qq] = 1.f / ss;
    }
    __syncthreads();

    int cq0 = (tid >> 4) * 4;
    int cd0 = (tid & 15) * 6;
    float cacc[4][6];
#pragma unroll
    for (int a = 0; a < 4; a++)
#pragma unroll
        for (int k = 0; k < 6; k++) cacc[a][k] = 0.f;

    for (int s = 0; s < NKBS; s++) {
        if (!val[s]) continue;
        __syncthreads();
        int kbase = b * SEQ + kbv[s] * BLKS;
        for (int idx = tid; idx < BLKS * HDIM; idx += 256) {
            int p = idx / HDIM, d = idx % HDIM;
            kv[p * VS + d] = V[(size_t)(kbase + p) * DMODEL + hh * HDIM + d];
        }
        __syncthreads();
#pragma unroll 2
        for (int p = 0; p < BLKS; p++) {
            float pr0 = sc[(cq0 + 0) * SCS + s * BLKS + p];
            float pr1 = sc[(cq0 + 1) * SCS + s * BLKS + p];
            float pr2 = sc[(cq0 + 2) * SCS + s * BLKS + p];
            float pr3 = sc[(cq0 + 3) * SCS + s * BLKS + p];
            const float* vp = &kv[p * VS + cd0];
#pragma unroll
            for (int k = 0; k < 6; k++) {
                float vv = vp[k];
                cacc[0][k] += pr0 * vv;
                cacc[1][k] += pr1 * vv;
                cacc[2][k] += pr2 * vv;
                cacc[3][k] += pr3 * vv;
            }
        }
    }

#pragma unroll
    for (int a = 0; a < 4; a++) {
        float rv = rinv[cq0 + a];
        size_t hiOff = ((size_t)(base + cq0 + a) * 2) * DMODEL + hh * HDIM + cd0;
#pragma unroll
        for (int k = 0; k < 6; k++) {
            __nv_bfloat16 h, l;
            split_bf(cacc[a][k] * rv, h, l);
            ctxP[hiOff + k]          = h;
            ctxP[hiOff + DMODEL + k] = l;
        }
    }
}

// ---------------- host launcher ----------------
extern "C" void kernel_launch(void* const* d_in, const int* in_sizes, int n_in,
                              void* d_out, int out_size) {
    const float* x    = (const float*)d_in[0];
    const float* Wq   = (const float*)d_in[1];
    const float* bq   = (const float*)d_in[2];
    const float* Wk   = (const float*)d_in[3];
    const float* bk   = (const float*)d_in[4];
    const float* Wv   = (const float*)d_in[5];
    const float* bv   = (const float*)d_in[6];
    const float* Wo   = (const float*)d_in[7];
    const float* bo   = (const float*)d_in[8];
    const float* ln_g = (const float*)d_in[9];
    const float* ln_b = (const float*)d_in[10];
    const float* W1   = (const float*)d_in[11];
    const float* b1   = (const float*)d_in[12];
    const float* W2   = (const float*)d_in[13];
    const float* b2   = (const float*)d_in[14];
    const int*   kb   = (const int*)d_in[15];
    float* out = (float*)d_out;

    __nv_bfloat16 *phP, *pctxP, *pffnP, *wqT, *wkT, *wvT, *woT, *w1T, *w2T;
    float *pq, *pk, *pv, *px;
    cudaGetSymbolAddress((void**)&phP,   g_hP);
    cudaGetSymbolAddress((void**)&pctxP, g_ctxP);
    cudaGetSymbolAddress((void**)&pffnP, g_ffnP);
    cudaGetSymbolAddress((void**)&pq,    g_q);
    cudaGetSymbolAddress((void**)&pk,    g_k);
    cudaGetSymbolAddress((void**)&pv,    g_v);
    cudaGetSymbolAddress((void**)&px,    g_x);
    cudaGetSymbolAddress((void**)&wqT,   g_wqT);
    cudaGetSymbolAddress((void**)&wkT,   g_wkT);
    cudaGetSymbolAddress((void**)&wvT,   g_wvT);
    cudaGetSymbolAddress((void**)&woT,   g_woT);
    cudaGetSymbolAddress((void**)&w1T,   g_w1T);
    cudaGetSymbolAddress((void**)&w2T,   g_w2T);

    cudaFuncSetAttribute(attn_kernel, cudaFuncAttributeMaxDynamicSharedMemorySize,
                         ATTN_SMEM_BYTES);
    cudaFuncSetAttribute(gemm_bf3_kernel, cudaFuncAttributeMaxDynamicSharedMemorySize,
                         GSMEM);

    dim3 gProj(DMODEL / 128, TOKENS / 128);   // (6,128)
    dim3 gFfn1(DFFN / 128, TOKENS / 128);     // (24,128)
    dim3 tDD(DMODEL / 32, DMODEL / 32);

    // launch order arranged so ncu (-s 5) samples gemmQ
    ln_pack_kernel<<<TOKENS, 256>>>(x, ln_g, ln_b, phP);                          // 0
    transpose_pack_kernel<<<tDD, 256>>>(Wq, wqT, DMODEL, DMODEL);                 // 1
    transpose_pack_kernel<<<tDD, 256>>>(Wk, wkT, DMODEL, DMODEL);                 // 2
    transpose_pack_kernel<<<tDD, 256>>>(Wv, wvT, DMODEL, DMODEL);                 // 3
    transpose_pack_kernel<<<tDD, 256>>>(Wo, woT, DMODEL, DMODEL);                 // 4
    gemm_bf3_kernel<<<gProj, 256, GSMEM>>>(phP, wqT, bq, nullptr, pq, nullptr,    // 5
                                           DMODEL, DMODEL, 0);
    gemm_bf3_kernel<<<gProj, 256, GSMEM>>>(phP, wkT, bk, nullptr, pk, nullptr,    // 6
                                           DMODEL, DMODEL, 0);
    gemm_bf3_kernel<<<gProj, 256, GSMEM>>>(phP, wvT, bv, nullptr, pv, nullptr,    // 7
                                           DMODEL, DMODEL, 0);
    attn_kernel<<<dim3(NBLK, NHEAD, BATCH), 256, ATTN_SMEM_BYTES>>>(pq, pk, pv,   // 8
                                                                    kb, pctxP);
    gemm_bf3_kernel<<<gProj, 256, GSMEM>>>(pctxP, woT, bo, x, px, nullptr,        // 9
                                           DMODEL, DMODEL, 0);
    ln_pack_kernel<<<TOKENS, 256>>>(px, ln_g, ln_b, phP);                         // 10
    transpose_pack_kernel<<<dim3(DFFN / 32, DMODEL / 32), 256>>>(W1, w1T,         // 11
                                                                 DMODEL, DFFN);
    transpose_pack_kernel<<<dim3(DMODEL / 32, DFFN / 32), 256>>>(W2, w2T,         // 12
                                                                 DFFN, DMODEL);
    gemm_bf3_kernel<<<gFfn1, 256, GSMEM>>>(phP, w1T, b1, nullptr, nullptr, pffnP, // 13
                                           DMODEL, DFFN, 1);
    gemm_bf3_kernel<<<gProj, 256, GSMEM>>>(pffnP, w2T, b2, px, out, nullptr,      // 14
                                           DFFN, DMODEL, 0);
}